// round 5
// baseline (speedup 1.0000x reference)
#include <cuda_runtime.h>
#include <cuda_bf16.h>

typedef unsigned long long ull;

#define H 256
#define S 200
#define BSZ 1024
#define BT 8
#define NITEMS 50000
#define KC 48            // k-pair slabs of W1/W2 cached in smem (of 128)

// ---------------- device globals (scratch; no allocs allowed) ----------------
__device__ ull   g_WhhP[128 * 768];          // packed (k,k+1) pairs, kp-major
__device__ ull   g_W1P[128 * 256];
__device__ ull   g_W2P[128 * 256];
__device__ float g_Etab[(size_t)NITEMS * 768];  // item_emb @ W_ih^T + b_ih
__device__ float g_hfin[BSZ * H];

// ---------------- f32x2 helpers ----------------
__device__ __forceinline__ void ffma2(ull& d, ull a, ull b) {
    asm("fma.rn.f32x2 %0, %1, %2, %3;" : "=l"(d) : "l"(a), "l"(b), "l"(d));
}
__device__ __forceinline__ ull pack2(float lo, float hi) {
    ull r; asm("mov.b64 %0, {%1, %2};" : "=l"(r) : "f"(lo), "f"(hi)); return r;
}
__device__ __forceinline__ void unpack2(ull v, float& lo, float& hi) {
    asm("mov.b64 {%0, %1}, %2;" : "=f"(lo), "=f"(hi) : "l"(v));
}
__device__ __forceinline__ float hsum2(ull v) {
    float lo, hi; unpack2(v, lo, hi); return lo + hi;
}
__device__ __forceinline__ float sigm(float v) { return 1.0f / (1.0f + __expf(-v)); }
__device__ __forceinline__ float ftanh(float v) {
    float e = __expf(2.0f * v);
    return 1.0f - 2.0f / (e + 1.0f);
}

// ---------------- weight packing ----------------
__global__ void prep_pack(const float* __restrict__ W_hh,
                          const float* __restrict__ W1,
                          const float* __restrict__ W2)
{
    int i = blockIdx.x * blockDim.x + threadIdx.x;
    if (i < 128 * 768) {
        int kp = i / 768, m = i % 768;
        g_WhhP[i] = pack2(W_hh[m * H + 2 * kp], W_hh[m * H + 2 * kp + 1]);
    }
    if (i < 128 * 256) {
        int kp = i / 256, jo = i % 256;
        g_W1P[i] = pack2(W1[jo * H + 2 * kp], W1[jo * H + 2 * kp + 1]);
        g_W2P[i] = pack2(W2[jo * H + 2 * kp], W2[jo * H + 2 * kp + 1]);
    }
}

// ---------------- generic C[M,N] = A[M,256] @ B[N,256]^T + bias ----------------
#define GM 32
#define GN 256

__global__ void __launch_bounds__(256) gemm_nt(
    const float* __restrict__ A, const float* __restrict__ B,
    const float* __restrict__ bias, float* __restrict__ C,
    int M, int N)
{
    __shared__ float shA[GM][H];       // 32 KB
    __shared__ float shW[8][GN + 8];   // 8 x 264 floats, rows 16B-aligned

    const int n0 = blockIdx.x * GN;
    const int m0 = blockIdx.y * GM;
    const int tid = threadIdx.x;

    // load A tile, vectorized (guarded)
#pragma unroll
    for (int i = 0; i < 8; i++) {
        int idx = tid + i * 256;              // 0..2047 float4s
        int r = idx >> 6, c4 = idx & 63;
        int m = m0 + r;
        float4 v = make_float4(0.f, 0.f, 0.f, 0.f);
        if (m < M) v = *(const float4*)&A[(size_t)m * H + c4 * 4];
        *(float4*)&shA[r][c4 * 4] = v;
    }

    const int tn = tid & 31;    // 32 n-groups of 8 columns
    const int tb = tid >> 5;    // 8 b-groups of 4 rows
    const int nl0 = tn * 8;

    ull acc[4][4];
#pragma unroll
    for (int bb = 0; bb < 4; bb++)
#pragma unroll
        for (int q = 0; q < 4; q++) acc[bb][q] = 0ull;

    __syncthreads();

    for (int k0 = 0; k0 < H; k0 += 8) {
        // stage W[n0..n0+255][k0..k0+7] transposed (coalesced reads)
#pragma unroll
        for (int i = 0; i < 8; i++) {
            int idx = tid + i * 256;          // 0..2047
            int nl = idx >> 3, kc = idx & 7;
            int n = n0 + nl;
            shW[kc][nl] = (n < N) ? B[(size_t)n * H + k0 + kc] : 0.f;
        }
        __syncthreads();
#pragma unroll
        for (int kc = 0; kc < 8; kc++) {
            ulonglong2 w01 = *(const ulonglong2*)&shW[kc][nl0];
            ulonglong2 w23 = *(const ulonglong2*)&shW[kc][nl0 + 4];
#pragma unroll
            for (int bb = 0; bb < 4; bb++) {
                float hb = shA[tb * 4 + bb][k0 + kc];
                ull hp = pack2(hb, hb);
                ffma2(acc[bb][0], hp, w01.x);
                ffma2(acc[bb][1], hp, w01.y);
                ffma2(acc[bb][2], hp, w23.x);
                ffma2(acc[bb][3], hp, w23.y);
            }
        }
        __syncthreads();
    }

    const int nbase = n0 + nl0;
#pragma unroll
    for (int bb = 0; bb < 4; bb++) {
        int m = m0 + tb * 4 + bb;
        if (m >= M) continue;
        float o[8];
        unpack2(acc[bb][0], o[0], o[1]);
        unpack2(acc[bb][1], o[2], o[3]);
        unpack2(acc[bb][2], o[4], o[5]);
        unpack2(acc[bb][3], o[6], o[7]);
        if (nbase + 7 < N) {
            float4 v0, v1;
            v0.x = o[0] + bias[nbase + 0]; v0.y = o[1] + bias[nbase + 1];
            v0.z = o[2] + bias[nbase + 2]; v0.w = o[3] + bias[nbase + 3];
            v1.x = o[4] + bias[nbase + 4]; v1.y = o[5] + bias[nbase + 5];
            v1.z = o[6] + bias[nbase + 6]; v1.w = o[7] + bias[nbase + 7];
            *(float4*)&C[(size_t)m * N + nbase] = v0;
            *(float4*)&C[(size_t)m * N + nbase + 4] = v1;
        } else {
#pragma unroll
            for (int q = 0; q < 8; q++) {
                int n = nbase + q;
                if (n < N) C[(size_t)m * N + n] = o[q] + bias[n];
            }
        }
    }
}

// ---------------- ODE matmul: out[r] = sum_k src[r][k] * W[col j][k] ----------------
// Cached part from smem; global part software-pipelined (8-kp groups, 1-group prefetch).
__device__ __forceinline__ void mm_ode(const float (*__restrict__ src)[H],
                                       const ull* __restrict__ ws,   // smem, kp < KC
                                       const ull* __restrict__ wg,   // global, full
                                       int j, float* out)
{
    ull acc[BT];
#pragma unroll
    for (int r = 0; r < BT; r++) acc[r] = 0ull;

    // ---- cached slabs ----
#pragma unroll 4
    for (int kp = 0; kp < KC; kp += 2) {
        ulonglong2 sv[BT];
#pragma unroll
        for (int r = 0; r < BT; r++) sv[r] = *(const ulonglong2*)&src[r][2 * kp];
        ull w0 = ws[kp * H + j];
        ull w1 = ws[(kp + 1) * H + j];
#pragma unroll
        for (int r = 0; r < BT; r++) { ffma2(acc[r], sv[r].x, w0); ffma2(acc[r], sv[r].y, w1); }
    }

    // ---- global slabs: (128-KC)=80 kp in 10 groups of 8, prefetch next group ----
    ull wc[8];
#pragma unroll
    for (int q = 0; q < 8; q++) wc[q] = wg[(KC + q) * H + j];

#pragma unroll 1
    for (int g = 0; g < 10; g++) {
        ull wn[8];
        if (g < 9) {
#pragma unroll
            for (int q = 0; q < 8; q++) wn[q] = wg[(KC + (g + 1) * 8 + q) * H + j];
        }
#pragma unroll
        for (int qq = 0; qq < 4; qq++) {
            ulonglong2 sv[BT];
#pragma unroll
            for (int r = 0; r < BT; r++)
                sv[r] = *(const ulonglong2*)&src[r][2 * (KC + g * 8) + qq * 4];
#pragma unroll
            for (int r = 0; r < BT; r++) {
                ffma2(acc[r], sv[r].x, wc[2 * qq]);
                ffma2(acc[r], sv[r].y, wc[2 * qq + 1]);
            }
        }
        if (g < 9) {
#pragma unroll
            for (int q = 0; q < 8; q++) wc[q] = wn[q];
        }
    }
#pragma unroll
    for (int r = 0; r < BT; r++) out[r] = hsum2(acc[r]);
}

__device__ __forceinline__ void ode_f(const float (*__restrict__ src)[H],
                                      float (*__restrict__ sh_a)[H],
                                      const ull* __restrict__ sW1,
                                      const ull* __restrict__ sW2,
                                      float* kv, int j, float b1j, float b2j)
{
    float t1[BT];
    mm_ode(src, sW1, g_W1P, j, t1);
#pragma unroll
    for (int r = 0; r < BT; r++) sh_a[r][j] = ftanh(t1[r] + b1j);
    __syncthreads();
    mm_ode(sh_a, sW2, g_W2P, j, kv);
#pragma unroll
    for (int r = 0; r < BT; r++) kv[r] += b2j;
}

// ---------------- recurrent kernel ----------------
__global__ void __launch_bounds__(256) rec_kernel(
    const int* __restrict__ x, const float* __restrict__ tt,
    const float* __restrict__ b_hh,
    const float* __restrict__ b1, const float* __restrict__ b2)
{
    extern __shared__ ull dynsmem[];
    ull* sW1 = dynsmem;                          // KC*256 ull
    ull* sW2 = dynsmem + KC * H;                 // KC*256 ull
    float* fbase = (float*)(dynsmem + 2 * KC * H);
    float (*sh_h)[H] = (float (*)[H])fbase;
    float (*sh_a)[H] = (float (*)[H])(fbase + BT * H);
    float (*sh_t)[H] = (float (*)[H])(fbase + 2 * BT * H);
    int*   sh_it = (int*)(fbase + 3 * BT * H);
    float* sh_dt = (float*)(sh_it + BT);

    const int j = threadIdx.x;
    const int b0 = blockIdx.x * BT;

    // cache first KC k-pair slabs of W1/W2 in smem (reused 200 steps x 4 evals)
    for (int i = j; i < KC * H; i += H) { sW1[i] = g_W1P[i]; sW2[i] = g_W2P[i]; }

    const float bhhr = b_hh[j], bhhz = b_hh[H + j], bhhn = b_hh[2 * H + j];
    const float b1j = b1[j], b2j = b2[j];

#pragma unroll
    for (int r = 0; r < BT; r++) sh_h[r][j] = 0.f;
    float hnew[BT];
#pragma unroll
    for (int r = 0; r < BT; r++) hnew[r] = 0.f;
    __syncthreads();

    const ull* __restrict__ whh = g_WhhP;

    for (int s = 0; s < S; s++) {
        if (j < BT) {
            sh_it[j] = x[(b0 + j) * S + s];
            float tc = tt[(b0 + j) * S + s];
            float d = 0.f;
            if (s < S - 1) {
                float tn = tt[(b0 + j) * S + s + 1];
                d = fmaxf(tn, tc + 1e-5f) - tc;
            }
            sh_dt[j] = d;
        }
        __syncthreads();   // (A)

        // issue input-gate gathers early (long-latency global loads)
        float giR[BT], giZ[BT], giN[BT];
#pragma unroll
        for (int r = 0; r < BT; r++) {
            const float* e = g_Etab + (size_t)sh_it[r] * 768;
            giR[r] = e[j];
            giZ[r] = e[H + j];
            giN[r] = e[2 * H + j];
        }

        // ---- hidden-state gate matmul: h @ W_hh^T ----
        // 32 groups of 4 kp; next group's 12 weight pairs prefetched while computing.
        ull aR[BT], aZ[BT], aN[BT];
#pragma unroll
        for (int r = 0; r < BT; r++) { aR[r] = 0ull; aZ[r] = 0ull; aN[r] = 0ull; }

        ull wb[12];
#pragma unroll
        for (int q = 0; q < 4; q++) {
            const ull* p = whh + (size_t)q * 768 + j;
            wb[3 * q] = p[0]; wb[3 * q + 1] = p[256]; wb[3 * q + 2] = p[512];
        }

#pragma unroll 1
        for (int g = 0; g < 32; g++) {
            ull wn[12];
            if (g < 31) {
#pragma unroll
                for (int q = 0; q < 4; q++) {
                    const ull* p = whh + (size_t)((g + 1) * 4 + q) * 768 + j;
                    wn[3 * q] = p[0]; wn[3 * q + 1] = p[256]; wn[3 * q + 2] = p[512];
                }
            }
#pragma unroll
            for (int qq = 0; qq < 2; qq++) {
                ulonglong2 hv[BT];
#pragma unroll
                for (int r = 0; r < BT; r++)
                    hv[r] = *(const ulonglong2*)&sh_h[r][g * 8 + qq * 4];
#pragma unroll
                for (int r = 0; r < BT; r++) {
                    ffma2(aR[r], hv[r].x, wb[6 * qq + 0]);
                    ffma2(aZ[r], hv[r].x, wb[6 * qq + 1]);
                    ffma2(aN[r], hv[r].x, wb[6 * qq + 2]);
                    ffma2(aR[r], hv[r].y, wb[6 * qq + 3]);
                    ffma2(aZ[r], hv[r].y, wb[6 * qq + 4]);
                    ffma2(aN[r], hv[r].y, wb[6 * qq + 5]);
                }
            }
            if (g < 31) {
#pragma unroll
                for (int q = 0; q < 12; q++) wb[q] = wn[q];
            }
        }

        // ---- GRU elementwise (gate order r,z,n) ----
#pragma unroll
        for (int r = 0; r < BT; r++) {
            float rg = sigm(giR[r] + hsum2(aR[r]) + bhhr);
            float zg = sigm(giZ[r] + hsum2(aZ[r]) + bhhz);
            float ng = ftanh(giN[r] + rg * (hsum2(aN[r]) + bhhn));
            hnew[r] = (1.f - zg) * ng + zg * sh_h[r][j];
        }
        __syncthreads();   // (B) everyone done reading sh_h
#pragma unroll
        for (int r = 0; r < BT; r++) sh_h[r][j] = hnew[r];
        __syncthreads();   // (C)

        // ---- RK4 ----
        float dtl[BT];
#pragma unroll
        for (int r = 0; r < BT; r++) dtl[r] = sh_dt[r];

        float kv[BT], ksum[BT];

        ode_f(sh_h, sh_a, sW1, sW2, kv, j, b1j, b2j);          // k1
#pragma unroll
        for (int r = 0; r < BT; r++) {
            ksum[r] = kv[r];
            sh_t[r][j] = hnew[r] + 0.5f * dtl[r] * kv[r];
        }
        __syncthreads();

        ode_f(sh_t, sh_a, sW1, sW2, kv, j, b1j, b2j);          // k2
#pragma unroll
        for (int r = 0; r < BT; r++) {
            ksum[r] += 2.f * kv[r];
            sh_t[r][j] = hnew[r] + 0.5f * dtl[r] * kv[r];
        }
        __syncthreads();

        ode_f(sh_t, sh_a, sW1, sW2, kv, j, b1j, b2j);          // k3
#pragma unroll
        for (int r = 0; r < BT; r++) {
            ksum[r] += 2.f * kv[r];
            sh_t[r][j] = hnew[r] + dtl[r] * kv[r];
        }
        __syncthreads();

        ode_f(sh_t, sh_a, sW1, sW2, kv, j, b1j, b2j);          // k4
#pragma unroll
        for (int r = 0; r < BT; r++) {
            ksum[r] += kv[r];
            hnew[r] = hnew[r] + (dtl[r] * (1.f / 6.f)) * ksum[r];
            sh_h[r][j] = hnew[r];
        }
        // next-iteration sync (A) fences sh_h / sh_it reuse
    }

#pragma unroll
    for (int r = 0; r < BT; r++) g_hfin[(b0 + r) * H + j] = hnew[r];
}

// ---------------- launch ----------------
extern "C" void kernel_launch(void* const* d_in, const int* in_sizes, int n_in,
                              void* d_out, int out_size)
{
    const int*   x      = (const int*)d_in[0];
    const float* t      = (const float*)d_in[1];
    const float* emb    = (const float*)d_in[2];
    const float* W_ih   = (const float*)d_in[3];
    const float* W_hh   = (const float*)d_in[4];
    const float* b_ih   = (const float*)d_in[5];
    const float* b_hh   = (const float*)d_in[6];
    const float* W1     = (const float*)d_in[7];
    const float* b1     = (const float*)d_in[8];
    const float* W2     = (const float*)d_in[9];
    const float* b2     = (const float*)d_in[10];
    const float* W_head = (const float*)d_in[11];
    const float* b_head = (const float*)d_in[12];
    float* out = (float*)d_out;

    float* etab_ptr = nullptr;
    float* hfin_ptr = nullptr;
    cudaGetSymbolAddress((void**)&etab_ptr, g_Etab);
    cudaGetSymbolAddress((void**)&hfin_ptr, g_hfin);

    const int smem_bytes = 2 * KC * H * (int)sizeof(ull) + 3 * BT * H * (int)sizeof(float)
                         + BT * (int)(sizeof(int) + sizeof(float));
    cudaFuncSetAttribute(rec_kernel, cudaFuncAttributeMaxDynamicSharedMemorySize, smem_bytes);

    prep_pack<<<(128 * 768 + 255) / 256, 256>>>(W_hh, W1, W2);

    // Etab = item_emb @ W_ih^T + b_ih   [50000, 768]
    dim3 ge(768 / GN, (NITEMS + GM - 1) / GM);
    gemm_nt<<<ge, 256>>>(emb, W_ih, b_ih, etab_ptr, NITEMS, 768);

    rec_kernel<<<BSZ / BT, H, smem_bytes>>>(x, t, b_hh, b1, b2);

    // out = h_fin @ W_head^T + b_head   [1024, 50000]
    dim3 gh((NITEMS + GN - 1) / GN, BSZ / GM);
    gemm_nt<<<gh, 256>>>(hfin_ptr, W_head, b_head, out, BSZ, NITEMS);
}

// round 6
// speedup vs baseline: 1.9298x; 1.9298x over previous
#include <cuda_runtime.h>
#include <cuda_bf16.h>

typedef unsigned long long ull;

#define H 256
#define S 200
#define BSZ 1024
#define BT 8
#define NITEMS 50000
#define KC 36            // k-pair slabs of W1/W2 cached in smem (of 128)

// ---------------- device globals (scratch; no allocs allowed) ----------------
__device__ ull   g_WhhP[128 * 768];          // packed (k,k+1) pairs, kp-major
__device__ ull   g_W1P[128 * 256];
__device__ ull   g_W2P[128 * 256];
__device__ float g_Etab[(size_t)NITEMS * 768];  // item_emb @ W_ih^T + b_ih
__device__ float g_hfin[BSZ * H];

// ---------------- f32x2 helpers ----------------
__device__ __forceinline__ void ffma2(ull& d, ull a, ull b) {
    asm("fma.rn.f32x2 %0, %1, %2, %3;" : "=l"(d) : "l"(a), "l"(b), "l"(d));
}
__device__ __forceinline__ ull pack2(float lo, float hi) {
    ull r; asm("mov.b64 %0, {%1, %2};" : "=l"(r) : "f"(lo), "f"(hi)); return r;
}
__device__ __forceinline__ void unpack2(ull v, float& lo, float& hi) {
    asm("mov.b64 {%0, %1}, %2;" : "=f"(lo), "=f"(hi) : "l"(v));
}
__device__ __forceinline__ float hsum2(ull v) {
    float lo, hi; unpack2(v, lo, hi); return lo + hi;
}
__device__ __forceinline__ float sigm(float v) { return 1.0f / (1.0f + __expf(-v)); }
__device__ __forceinline__ float ftanh(float v) {
    float e = __expf(2.0f * v);
    return 1.0f - 2.0f / (e + 1.0f);
}

// ---------------- weight packing ----------------
__global__ void prep_pack(const float* __restrict__ W_hh,
                          const float* __restrict__ W1,
                          const float* __restrict__ W2)
{
    int i = blockIdx.x * blockDim.x + threadIdx.x;
    if (i < 128 * 768) {
        int kp = i / 768, m = i % 768;
        g_WhhP[i] = pack2(W_hh[m * H + 2 * kp], W_hh[m * H + 2 * kp + 1]);
    }
    if (i < 128 * 256) {
        int kp = i / 256, jo = i % 256;
        g_W1P[i] = pack2(W1[jo * H + 2 * kp], W1[jo * H + 2 * kp + 1]);
        g_W2P[i] = pack2(W2[jo * H + 2 * kp], W2[jo * H + 2 * kp + 1]);
    }
}

// ---------------- generic C[M,N] = A[M,256] @ B[N,256]^T + bias ----------------
#define GM 64
#define GN 128

__global__ void __launch_bounds__(256) gemm_nt(
    const float* __restrict__ A, const float* __restrict__ B,
    const float* __restrict__ bias, float* __restrict__ C,
    int M, int N)
{
    __shared__ float shA[GM][H];     // 64 KB
    __shared__ float shW[8][132];    // staged W chunk (padded)

    const int n0 = blockIdx.x * GN;
    const int m0 = blockIdx.y * GM;
    const int tid = threadIdx.x;

    // load A tile, vectorized, guarded
#pragma unroll
    for (int i = 0; i < 16; i++) {
        int idx = tid + i * 256;              // 0..4095 float4s
        int r = idx >> 6, c4 = idx & 63;
        int m = m0 + r;
        float4 v = make_float4(0.f, 0.f, 0.f, 0.f);
        if (m < M) v = *(const float4*)&A[(size_t)m * H + c4 * 4];
        *(float4*)&shA[r][c4 * 4] = v;
    }

    const int tn = tid & 31;   // 32 n-groups of 4 cols
    const int tb = tid >> 5;   // 8 b-groups of 8 rows
    const int nl0 = tn * 4;

    ull acc[8][2];
#pragma unroll
    for (int bb = 0; bb < 8; bb++) { acc[bb][0] = 0ull; acc[bb][1] = 0ull; }

    __syncthreads();

    for (int k0 = 0; k0 < H; k0 += 8) {
#pragma unroll
        for (int i = 0; i < 4; i++) {
            int idx = tid + i * 256;          // 0..1023 -> 128 n x 8 k
            int nl = idx >> 3, kc = idx & 7;
            int n = n0 + nl;
            shW[kc][nl] = (n < N) ? B[(size_t)n * H + k0 + kc] : 0.f;
        }
        __syncthreads();
#pragma unroll
        for (int kc = 0; kc < 8; kc++) {
            ulonglong2 wv = *(const ulonglong2*)&shW[kc][nl0];
#pragma unroll
            for (int bb = 0; bb < 8; bb++) {
                float hb = shA[tb * 8 + bb][k0 + kc];
                ull hp = pack2(hb, hb);
                ffma2(acc[bb][0], hp, wv.x);
                ffma2(acc[bb][1], hp, wv.y);
            }
        }
        __syncthreads();
    }

    const int nbase = n0 + nl0;
#pragma unroll
    for (int bb = 0; bb < 8; bb++) {
        int m = m0 + tb * 8 + bb;
        if (m >= M) continue;
        float o0, o1, o2, o3;
        unpack2(acc[bb][0], o0, o1);
        unpack2(acc[bb][1], o2, o3);
        if (nbase + 3 < N) {
            float4 o;
            o.x = o0 + bias[nbase + 0];
            o.y = o1 + bias[nbase + 1];
            o.z = o2 + bias[nbase + 2];
            o.w = o3 + bias[nbase + 3];
            *(float4*)&C[(size_t)m * N + nbase] = o;
        } else {
            float ov[4] = {o0, o1, o2, o3};
#pragma unroll
            for (int nn = 0; nn < 4; nn++) {
                int n = nbase + nn;
                if (n < N) C[(size_t)m * N + n] = ov[nn] + bias[n];
            }
        }
    }
}

// ---------------- ODE partial matmul over this half's kp range ----------------
// acc[r] += sum_{kp in half's range} src[r][2kp..2kp+1] * W[col j][kp]
__device__ __forceinline__ void mm_partial(const float (*__restrict__ src)[H],
                                           const ull* __restrict__ ws,   // smem cached, kp<KC
                                           const ull* __restrict__ wg,   // global, full
                                           int j, int half, ull* acc)
{
#pragma unroll
    for (int r = 0; r < BT; r++) acc[r] = 0ull;

    // cached: 18 kp per half  [half*18, half*18+18)
    const int kc0 = half * 18;
#pragma unroll 3
    for (int c = 0; c < 9; c++) {
        int kp = kc0 + 2 * c;
        ull w0 = ws[kp * H + j];
        ull w1 = ws[(kp + 1) * H + j];
#pragma unroll
        for (int r = 0; r < BT; r++) {
            ulonglong2 sv = *(const ulonglong2*)&src[r][2 * kp];
            ffma2(acc[r], sv.x, w0);
            ffma2(acc[r], sv.y, w1);
        }
    }

    // global: 46 kp per half  [KC + half*46, KC + half*46 + 46)
    const int kg0 = KC + half * 46;
#pragma unroll 2
    for (int c = 0; c < 23; c++) {
        int kp = kg0 + 2 * c;
        ull w0 = wg[kp * H + j];
        ull w1 = wg[(kp + 1) * H + j];
#pragma unroll
        for (int r = 0; r < BT; r++) {
            ulonglong2 sv = *(const ulonglong2*)&src[r][2 * kp];
            ffma2(acc[r], sv.x, w0);
            ffma2(acc[r], sv.y, w1);
        }
    }
}

// ---------------- recurrent kernel: 512 threads, K split across 2 halves ----------------
__global__ void __launch_bounds__(512) rec_kernel(
    const int* __restrict__ x, const float* __restrict__ tt,
    const float* __restrict__ b_hh,
    const float* __restrict__ b1, const float* __restrict__ b2)
{
    extern __shared__ ull dynsmem[];
    ull* sW1 = dynsmem;                          // KC*256 ull
    ull* sW2 = dynsmem + KC * H;                 // KC*256 ull
    float* fbase = (float*)(dynsmem + 2 * KC * H);
    float (*sh_h)[H] = (float (*)[H])fbase;                  // 8x256
    float (*sh_a)[H] = (float (*)[H])(fbase + BT * H);       // 8x256
    float (*sh_t)[H] = (float (*)[H])(fbase + 2 * BT * H);   // 8x256
    float* red = fbase + 3 * BT * H;                         // 2*3*8*256 floats (48 KB)
    int*   sh_it = (int*)(red + 2 * 3 * BT * H);
    float* sh_dt = (float*)(sh_it + BT);

    const int tid = threadIdx.x;
    const int j = tid & 255;
    const int half = tid >> 8;
    const int r0 = half * 4;                     // this thread's 4 rows
    const int b0 = blockIdx.x * BT;

    // reduction index: plane (h,g,r) at ((h*3+g)*8 + r)*H + j
#define RG(hh, g, r) ((((hh) * 3 + (g)) * 8 + (r)) * H + j)

    // cache KC k-pair slabs of W1/W2 in smem
    for (int i = tid; i < KC * H; i += 512) { sW1[i] = g_W1P[i]; sW2[i] = g_W2P[i]; }

    const float bhhr = b_hh[j], bhhz = b_hh[H + j], bhhn = b_hh[2 * H + j];
    const float b1j = b1[j], b2j = b2[j];

#pragma unroll
    for (int q = 0; q < 4; q++) sh_h[r0 + q][j] = 0.f;
    float hnew[4];
#pragma unroll
    for (int q = 0; q < 4; q++) hnew[q] = 0.f;
    __syncthreads();

    const ull* __restrict__ whh = g_WhhP;

    for (int s = 0; s < S; s++) {
        if (tid < BT) {
            sh_it[tid] = x[(b0 + tid) * S + s];
            float tc = tt[(b0 + tid) * S + s];
            float d = 0.f;
            if (s < S - 1) {
                float tn = tt[(b0 + tid) * S + s + 1];
                d = fmaxf(tn, tc + 1e-5f) - tc;
            }
            sh_dt[tid] = d;
        }
        __syncthreads();   // (A)

        // input-gate gathers for this thread's 4 rows (long-latency, issue early)
        float giR[4], giZ[4], giN[4], dt4[4];
#pragma unroll
        for (int q = 0; q < 4; q++) {
            const float* e = g_Etab + (size_t)sh_it[r0 + q] * 768;
            giR[q] = e[j];
            giZ[q] = e[H + j];
            giN[q] = e[2 * H + j];
            dt4[q] = sh_dt[r0 + q];
        }

        // ---- GRU partial gate matmul over this half's 64 kp ----
        ull aR[BT], aZ[BT], aN[BT];
#pragma unroll
        for (int r = 0; r < BT; r++) { aR[r] = 0ull; aZ[r] = 0ull; aN[r] = 0ull; }

        const int kpb = half * 64;
#pragma unroll 2
        for (int p = 0; p < 32; p++) {
            const int kp = kpb + 2 * p;
            const ull* wp = whh + (size_t)kp * 768 + j;
            ull w0R = wp[0],   w0Z = wp[256],  w0N = wp[512];
            ull w1R = wp[768], w1Z = wp[1024], w1N = wp[1280];
#pragma unroll
            for (int r = 0; r < BT; r++) {
                ulonglong2 hv = *(const ulonglong2*)&sh_h[r][2 * kp];
                ffma2(aR[r], hv.x, w0R);
                ffma2(aZ[r], hv.x, w0Z);
                ffma2(aN[r], hv.x, w0N);
                ffma2(aR[r], hv.y, w1R);
                ffma2(aZ[r], hv.y, w1Z);
                ffma2(aN[r], hv.y, w1N);
            }
        }

        // write partials
#pragma unroll
        for (int r = 0; r < BT; r++) {
            red[RG(half, 0, r)] = hsum2(aR[r]);
            red[RG(half, 1, r)] = hsum2(aZ[r]);
            red[RG(half, 2, r)] = hsum2(aN[r]);
        }
        __syncthreads();

        // combine + GRU elementwise for this thread's 4 rows
#pragma unroll
        for (int q = 0; q < 4; q++) {
            int r = r0 + q;
            float pR = red[RG(0, 0, r)] + red[RG(1, 0, r)];
            float pZ = red[RG(0, 1, r)] + red[RG(1, 1, r)];
            float pN = red[RG(0, 2, r)] + red[RG(1, 2, r)];
            float rg = sigm(giR[q] + pR + bhhr);
            float zg = sigm(giZ[q] + pZ + bhhz);
            float ng = ftanh(giN[q] + rg * (pN + bhhn));
            float hold = sh_h[r][j];
            hnew[q] = (1.f - zg) * ng + zg * hold;
            sh_h[r][j] = hnew[q];
        }
        __syncthreads();

        // ---- RK4 ----
        float ksum[4], kv[4];
        ull acc[BT];
        float (*src)[H] = sh_h;

#pragma unroll 1
        for (int eval = 0; eval < 4; eval++) {
            // layer 1
            mm_partial(src, sW1, g_W1P, j, half, acc);
#pragma unroll
            for (int r = 0; r < BT; r++) red[RG(half, 0, r)] = hsum2(acc[r]);
            __syncthreads();
#pragma unroll
            for (int q = 0; q < 4; q++) {
                int r = r0 + q;
                sh_a[r][j] = ftanh(red[RG(0, 0, r)] + red[RG(1, 0, r)] + b1j);
            }
            __syncthreads();

            // layer 2
            mm_partial(sh_a, sW2, g_W2P, j, half, acc);
#pragma unroll
            for (int r = 0; r < BT; r++) red[RG(half, 0, r)] = hsum2(acc[r]);
            __syncthreads();
#pragma unroll
            for (int q = 0; q < 4; q++) {
                int r = r0 + q;
                kv[q] = red[RG(0, 0, r)] + red[RG(1, 0, r)] + b2j;
            }

            // RK4 bookkeeping + write next src (this thread's rows only)
            if (eval == 0) {
#pragma unroll
                for (int q = 0; q < 4; q++) {
                    ksum[q] = kv[q];
                    sh_t[r0 + q][j] = hnew[q] + 0.5f * dt4[q] * kv[q];
                }
            } else if (eval == 1) {
#pragma unroll
                for (int q = 0; q < 4; q++) {
                    ksum[q] += 2.f * kv[q];
                    sh_t[r0 + q][j] = hnew[q] + 0.5f * dt4[q] * kv[q];
                }
            } else if (eval == 2) {
#pragma unroll
                for (int q = 0; q < 4; q++) {
                    ksum[q] += 2.f * kv[q];
                    sh_t[r0 + q][j] = hnew[q] + dt4[q] * kv[q];
                }
            } else {
#pragma unroll
                for (int q = 0; q < 4; q++) {
                    ksum[q] += kv[q];
                    hnew[q] = hnew[q] + (dt4[q] * (1.f / 6.f)) * ksum[q];
                    sh_h[r0 + q][j] = hnew[q];
                }
            }
            __syncthreads();   // sh_t/sh_h visible; red reusable
            src = sh_t;
        }
        // next-iteration (A) barrier fences sh_it/sh_dt reuse
    }

#pragma unroll
    for (int q = 0; q < 4; q++) g_hfin[(b0 + r0 + q) * H + j] = hnew[q];
#undef RG
}

// ---------------- launch ----------------
extern "C" void kernel_launch(void* const* d_in, const int* in_sizes, int n_in,
                              void* d_out, int out_size)
{
    const int*   x      = (const int*)d_in[0];
    const float* t      = (const float*)d_in[1];
    const float* emb    = (const float*)d_in[2];
    const float* W_ih   = (const float*)d_in[3];
    const float* W_hh   = (const float*)d_in[4];
    const float* b_ih   = (const float*)d_in[5];
    const float* b_hh   = (const float*)d_in[6];
    const float* W1     = (const float*)d_in[7];
    const float* b1     = (const float*)d_in[8];
    const float* W2     = (const float*)d_in[9];
    const float* b2     = (const float*)d_in[10];
    const float* W_head = (const float*)d_in[11];
    const float* b_head = (const float*)d_in[12];
    float* out = (float*)d_out;

    float* etab_ptr = nullptr;
    float* hfin_ptr = nullptr;
    cudaGetSymbolAddress((void**)&etab_ptr, g_Etab);
    cudaGetSymbolAddress((void**)&hfin_ptr, g_hfin);

    const int smem_bytes = 2 * KC * H * (int)sizeof(ull)            // W1/W2 cache
                         + 3 * BT * H * (int)sizeof(float)          // h/a/t
                         + 2 * 3 * BT * H * (int)sizeof(float)      // reduction buffer
                         + BT * (int)(sizeof(int) + sizeof(float)); // it/dt
    cudaFuncSetAttribute(rec_kernel, cudaFuncAttributeMaxDynamicSharedMemorySize, smem_bytes);

    prep_pack<<<(128 * 768 + 255) / 256, 256>>>(W_hh, W1, W2);

    // Etab = item_emb @ W_ih^T + b_ih   [50000, 768]
    dim3 ge(768 / GN, (NITEMS + GM - 1) / GM);
    gemm_nt<<<ge, 256>>>(emb, W_ih, b_ih, etab_ptr, NITEMS, 768);

    rec_kernel<<<BSZ / BT, 512, smem_bytes>>>(x, t, b_hh, b1, b2);

    // out = h_fin @ W_head^T + b_head   [1024, 50000]
    dim3 gh((NITEMS + GN - 1) / GN, BSZ / GM);
    gemm_nt<<<gh, 256>>>(hfin_ptr, W_head, b_head, out, BSZ, NITEMS);
}